// round 6
// baseline (speedup 1.0000x reference)
#include <cuda_runtime.h>
#include <cuda_bf16.h>
#include <mma.h>
#include <math.h>

using namespace nvcuda;

#define B_  4
#define HWC 4096
#define HWF 16384

typedef unsigned long long ull;
typedef unsigned int u32;
typedef unsigned short u16;

__device__ __forceinline__ ull pk2(float a, float b) {
    ull r; asm("mov.b64 %0, {%1,%2};" : "=l"(r) : "f"(a), "f"(b)); return r;
}
__device__ __forceinline__ ull fma2(ull a, ull b, ull c) {
    ull d; asm("fma.rn.f32x2 %0, %1, %2, %3;" : "=l"(d) : "l"(a), "l"(b), "l"(c)); return d;
}
__device__ __forceinline__ void unpk2(ull v, float& lo, float& hi) {
    asm("mov.b64 {%0,%1}, %2;" : "=f"(lo), "=f"(hi) : "l"(v));
}

// ---------------- scratch ----------------
__device__ float g_cm0[B_*3*HWC];
__device__ float g_warped1c[B_*64*HWC];
__device__ float g_xin[B_*130*HWC];
__device__ float g_cbuf0[B_*256*HWC];
__device__ float g_cbuf1[B_*256*HWC];
__device__ float g_cm[B_*3*HWC];
__device__ float g_up[B_*3*HWF];
__device__ float g_warped1f[B_*24*HWF];
__device__ float g_yin[B_*50*HWF];
__device__ float g_fbuf0[B_*64*HWF];
__device__ float g_fbuf1[B_*64*HWF];
__device__ float g_bnscale[256];
__device__ float g_bnshift[256];
__device__ u16   g_wHi[2359296];
__device__ u16   g_wLo[2359296];

// weight transform: [oc][cin][9] fp32 -> [tap][oc][icp] split bf16
__global__ void wtransform_kernel(const float* __restrict__ w, u16* __restrict__ whi,
                                  u16* __restrict__ wlo, int CIN, int CINp, int COUT) {
    int idx = blockIdx.x*256 + threadIdx.x;
    int total = 9*COUT*CINp;
    if (idx >= total) return;
    int t  = idx / (COUT*CINp);
    int r  = idx % (COUT*CINp);
    int oc = r / CINp, ic = r % CINp;
    float v = (ic < CIN) ? w[(oc*CIN + ic)*9 + t] : 0.0f;
    __nv_bfloat16 h = __float2bfloat16(v);
    __nv_bfloat16 l = __float2bfloat16(v - __bfloat162float(h));
    whi[idx] = __bfloat16_as_ushort(h);
    wlo[idx] = __bfloat16_as_ushort(l);
}

// ---------------- wmma split-bf16 implicit-GEMM 3x3 conv ----------------
// CTA: 128 px (TH rows x W) x N oc, N = 32*NTW (coarse NTW=4 -> 128, fine NTW=2 -> 64).
// X tile stored [pos][ic] (72-pad) so the A fragment of any tap is a pointer offset.
// 8 warps: mgrp = w&3 (2 m-tiles each), ngrp = w>>2 (NTW n-tiles each).
template<int NTW>
__global__ __launch_bounds__(256, 1)
void conv_wmma_kernel(const float* __restrict__ in, const u16* __restrict__ wHi,
                      const u16* __restrict__ wLo, float* __restrict__ out,
                      int H, int W, int CIN, int CINp, int COUT, int applyBn) {
    extern __shared__ u16 sm[];
    const int N   = 32*NTW;
    const int TH  = 128 / W;
    const int WP  = W + 2;
    const int POS = (TH + 2)*WP;
    const int HW  = H*W;
    const int tid = threadIdx.x;
    const int wid = tid >> 5;
    const int mgrp = wid & 3, ngrp = wid >> 2;
    const int b   = blockIdx.z;
    const int oc0 = blockIdx.y * N;
    const int th0 = blockIdx.x * TH;

    __nv_bfloat16* Xhi = (__nv_bfloat16*)sm;
    __nv_bfloat16* Xlo = Xhi + POS*72;
    __nv_bfloat16* Bhs = Xlo + POS*72;
    __nv_bfloat16* Bls = Bhs + N*72;

    wmma::fragment<wmma::accumulator,16,16,16,float> acc[2][NTW];
#pragma unroll
    for (int i = 0; i < 2; i++)
#pragma unroll
        for (int nt = 0; nt < NTW; nt++) wmma::fill_fragment(acc[i][nt], 0.0f);

    const int nIcc = CINp >> 6;
    for (int icc = 0; icc < nIcc; ++icc) {
        int ic0 = icc * 64;
        __syncthreads();
        // load X tile [pos][ic] with halo + split bf16 (+BN/relu)
        for (int idx = tid; idx < 64*POS; idx += 256) {
            int ic = idx / POS, pos = idx - ic*POS;
            int r = pos / WP, c = pos - r*WP;
            int gh = th0 + r - 1, gw = c - 1;
            int icg = ic0 + ic;
            float v = 0.0f;
            if (icg < CIN && gh >= 0 && gh < H && gw >= 0 && gw < W) {
                v = in[((size_t)(b*CIN + icg)*H + gh)*W + gw];
                if (applyBn) v = fmaxf(fmaf(v, g_bnscale[icg], g_bnshift[icg]), 0.0f);
            }
            __nv_bfloat16 h = __float2bfloat16(v);
            __nv_bfloat16 l = __float2bfloat16(v - __bfloat162float(h));
            Xhi[pos*72 + ic] = h;
            Xlo[pos*72 + ic] = l;
        }
        __syncthreads();

        for (int tap = 0; tap < 9; ++tap) {
            if (tap) __syncthreads();    // protect B smem from previous tap's readers
            // stage B [oc][ic] (col-major fragments), hi+lo
            for (int idx = tid; idx < N*64; idx += 256) {
                int oc = idx >> 6, ic = idx & 63;
                size_t src = ((size_t)(tap*COUT + oc0 + oc))*CINp + ic0 + ic;
                Bhs[oc*72 + ic] = __ushort_as_bfloat16(wHi[src]);
                Bls[oc*72 + ic] = __ushort_as_bfloat16(wLo[src]);
            }
            __syncthreads();

            int dh = tap / 3, dw = tap - dh*3;
#pragma unroll
            for (int kb = 0; kb < 4; ++kb) {
                wmma::fragment<wmma::matrix_a,16,16,16,__nv_bfloat16,wmma::row_major> Ah[2], Al[2];
#pragma unroll
                for (int i = 0; i < 2; i++) {
                    int mt = mgrp*2 + i;
                    int pr  = (TH == 2) ? (mt >> 2) : 0;
                    int pc0 = (TH == 2) ? ((mt & 3)*16) : mt*16;
                    int pos0 = (pr + dh)*WP + pc0 + dw;
                    wmma::load_matrix_sync(Ah[i], Xhi + pos0*72 + kb*16, 72);
                    wmma::load_matrix_sync(Al[i], Xlo + pos0*72 + kb*16, 72);
                }
#pragma unroll
                for (int nt = 0; nt < NTW; nt++) {
                    int n0 = (ngrp*NTW + nt)*16;
                    wmma::fragment<wmma::matrix_b,16,16,16,__nv_bfloat16,wmma::col_major> Bh, Bl;
                    wmma::load_matrix_sync(Bh, Bhs + n0*72 + kb*16, 72);
                    wmma::load_matrix_sync(Bl, Bls + n0*72 + kb*16, 72);
#pragma unroll
                    for (int i = 0; i < 2; i++) {
                        wmma::mma_sync(acc[i][nt], Ah[i], Bh, acc[i][nt]);
                        wmma::mma_sync(acc[i][nt], Ah[i], Bl, acc[i][nt]);
                        wmma::mma_sync(acc[i][nt], Al[i], Bh, acc[i][nt]);
                    }
                }
            }
        }
    }

    // store: out[oc][px] column-major tiles
#pragma unroll
    for (int i = 0; i < 2; i++) {
        int mt = mgrp*2 + i;
        int pr  = (TH == 2) ? (mt >> 2) : 0;
        int pc0 = (TH == 2) ? ((mt & 3)*16) : mt*16;
        int pxb = (th0 + pr)*W + pc0;
#pragma unroll
        for (int nt = 0; nt < NTW; nt++) {
            int oc = oc0 + (ngrp*NTW + nt)*16;
            wmma::store_matrix_sync(out + ((size_t)(b*COUT + oc))*HW + pxb,
                                    acc[i][nt], HW, wmma::mem_col_major);
        }
    }
}

// ---------------- attention (FFMA2) ----------------
__global__ void attention_kernel(const float* __restrict__ f0, const float* __restrict__ f1) {
    int b = blockIdx.y, h = blockIdx.x;
    int tid = threadIdx.x;
    __shared__ __align__(16) float q_s[64][66];
    __shared__ __align__(16) float k_s[64][66];
    const float* f0b = f0 + (size_t)b*64*HWC;
    const float* f1b = f1 + (size_t)b*64*HWC;
    for (int idx = tid; idx < 4096; idx += 256) {
        int c = idx >> 6, q = idx & 63;
        q_s[c][q] = f0b[c*HWC + h*64 + q];
    }
    int tq = tid >> 4, tk = tid & 15;
    float m[4], ss[4], px[4], py[4];
#pragma unroll
    for (int i = 0; i < 4; i++) { m[i] = -1e30f; ss[i] = 0.f; px[i] = 0.f; py[i] = 0.f; }
    for (int t = 0; t < 64; ++t) {
        __syncthreads();
        for (int idx = tid; idx < 4096; idx += 256) {
            int c = idx >> 6, j = idx & 63;
            k_s[c][j] = f1b[c*HWC + t*64 + j];
        }
        __syncthreads();
        ull acc2[4][2];
#pragma unroll
        for (int i = 0; i < 4; i++) { acc2[i][0] = 0ull; acc2[i][1] = 0ull; }
#pragma unroll 8
        for (int c = 0; c < 64; ++c) {
            ull k01 = *(const ull*)&k_s[c][tk*4];
            ull k23 = *(const ull*)&k_s[c][tk*4+2];
#pragma unroll
            for (int i = 0; i < 4; i++) {
                float q = q_s[c][tq*4+i];
                ull qq = pk2(q, q);
                acc2[i][0] = fma2(qq, k01, acc2[i][0]);
                acc2[i][1] = fma2(qq, k23, acc2[i][1]);
            }
        }
#pragma unroll
        for (int i = 0; i < 4; i++) {
            float sc[4];
            unpk2(acc2[i][0], sc[0], sc[1]);
            unpk2(acc2[i][1], sc[2], sc[3]);
            float mt = m[i];
#pragma unroll
            for (int j = 0; j < 4; j++) mt = fmaxf(mt, sc[j]*0.125f);
            float f = __expf(m[i] - mt);
            float es = 0.f, ex = 0.f, ey = 0.f;
#pragma unroll
            for (int j = 0; j < 4; j++) {
                int jj = t*64 + tk*4 + j;
                float e  = __expf(sc[j]*0.125f - mt);
                float gx = (float)(2*(jj & 63) + 1) * (1.0f/64.0f) - 1.0f;
                float gy = (float)(2*(jj >> 6) + 1) * (1.0f/64.0f) - 1.0f;
                es += e; ex += e*gx; ey += e*gy;
            }
            ss[i] = ss[i]*f + es; px[i] = px[i]*f + ex; py[i] = py[i]*f + ey; m[i] = mt;
        }
    }
    __syncthreads();
    float* red = &k_s[0][0];
#pragma unroll
    for (int i = 0; i < 4; i++) {
        int q = tq*4 + i;
        red[       q*16+tk] = m[i];
        red[1024 + q*16+tk] = ss[i];
        red[2048 + q*16+tk] = px[i];
        red[3072 + q*16+tk] = py[i];
    }
    __syncthreads();
    if (tid < 64) {
        int q = tid;
        float M = -1e30f;
        for (int t2 = 0; t2 < 16; t2++) M = fmaxf(M, red[q*16+t2]);
        float S = 0.f, X = 0.f, Y = 0.f;
        for (int t2 = 0; t2 < 16; t2++) {
            float f = __expf(red[q*16+t2] - M);
            S += red[1024 + q*16+t2]*f;
            X += red[2048 + q*16+t2]*f;
            Y += red[3072 + q*16+t2]*f;
        }
        int p = h*64 + q;
        g_cm0[(b*3+0)*HWC + p] = X / S;
        g_cm0[(b*3+1)*HWC + p] = Y / S;
        g_cm0[(b*3+2)*HWC + p] = 0.0f;
    }
}

__global__ void gridsample_kernel(const float* __restrict__ img, const float* __restrict__ cm,
                                  float* __restrict__ out, int C, int H, int W) {
    int idx = blockIdx.x*256 + threadIdx.x;
    int HW = H*W;
    int total = B_*C*HW;
    if (idx >= total) return;
    int p = idx % HW; int c = (idx / HW) % C; int b = idx / (HW*C);
    float gx = cm[(b*3+0)*HW + p];
    float gy = cm[(b*3+1)*HW + p];
    float x = (gx + 1.0f)*(W*0.5f) - 0.5f;
    float y = (gy + 1.0f)*(H*0.5f) - 0.5f;
    float x0f = floorf(x), y0f = floorf(y);
    float wx = x - x0f, wy = y - y0f;
    int x0 = (int)x0f, y0 = (int)y0f;
    const float* im = img + (size_t)(b*C + c)*HW;
    float v[4];
#pragma unroll
    for (int iy = 0; iy < 2; iy++)
#pragma unroll
        for (int ix = 0; ix < 2; ix++) {
            int xi = x0 + ix, yi = y0 + iy;
            bool valid = (xi >= 0 && xi < W && yi >= 0 && yi < H);
            int xc = min(max(xi, 0), W-1), yc = min(max(yi, 0), H-1);
            v[iy*2+ix] = valid ? im[yc*W + xc] : 0.0f;
        }
    out[idx] = v[0]*(1-wx)*(1-wy) + v[1]*wx*(1-wy) + v[2]*(1-wx)*wy + v[3]*wx*wy;
}

__global__ void concat_c_kernel(const float* __restrict__ f0c) {
    int idx = blockIdx.x*256 + threadIdx.x;
    if (idx >= B_*130*HWC) return;
    int p = idx % HWC; int c = (idx / HWC) % 130; int b = idx / (HWC*130);
    float v;
    if (c < 64)       v = f0c[(b*64 + c)*HWC + p];
    else if (c < 128) v = g_warped1c[(b*64 + (c-64))*HWC + p];
    else              v = g_cm0[(b*3 + (c-128))*HWC + p];
    g_xin[idx] = v;
}

__global__ void concat_f_kernel(const float* __restrict__ f0f) {
    int idx = blockIdx.x*256 + threadIdx.x;
    if (idx >= B_*50*HWF) return;
    int p = idx % HWF; int c = (idx / HWF) % 50; int b = idx / (HWF*50);
    float v;
    if (c < 24)      v = f0f[(b*24 + c)*HWF + p];
    else if (c < 48) v = g_warped1f[(b*24 + (c-24))*HWF + p];
    else             v = g_up[(b*3 + (c-48))*HWF + p];
    g_yin[idx] = v;
}

__global__ void bnstats_kernel(const float* __restrict__ in, int C, int HW) {
    int c = blockIdx.x;
    int tid = threadIdx.x;
    float s = 0.f, s2 = 0.f;
    for (int b = 0; b < B_; ++b) {
        const float* p = in + (size_t)(b*C + c)*HW;
        for (int i = tid; i < HW; i += 256) { float v = p[i]; s += v; s2 += v*v; }
    }
    __shared__ float sh[256], sh2[256];
    sh[tid] = s; sh2[tid] = s2;
    __syncthreads();
    for (int o = 128; o > 0; o >>= 1) {
        if (tid < o) { sh[tid] += sh[tid+o]; sh2[tid] += sh2[tid+o]; }
        __syncthreads();
    }
    if (tid == 0) {
        float n = (float)(B_*HW);
        float mean = sh[0] / n;
        float var  = sh2[0] / n - mean*mean;
        float sc = rsqrtf(var + 1e-5f);
        g_bnscale[c] = sc;
        g_bnshift[c] = -mean * sc;
    }
}

__global__ void conv1x1_kernel(const float* __restrict__ inbuf, const float* __restrict__ wgt,
                               const float* __restrict__ bias, const float* __restrict__ base,
                               float* __restrict__ dout, float* __restrict__ dup,
                               int CIN, int HW) {
    __shared__ float s_w[3*256], s_sc[256], s_sh[256];
    int tid = threadIdx.x;
    for (int i = tid; i < 3*CIN; i += 256) s_w[i] = wgt[i];
    for (int i = tid; i < CIN; i += 256) { s_sc[i] = g_bnscale[i]; s_sh[i] = g_bnshift[i]; }
    __syncthreads();
    int idx = blockIdx.x*256 + tid;
    int p = idx % HW, b = idx / HW;
    float a0 = bias[0], a1 = bias[1], a2 = bias[2];
    const float* ip = inbuf + (size_t)b*CIN*HW + p;
    for (int ic = 0; ic < CIN; ++ic) {
        float v = ip[(size_t)ic*HW];
        v = fmaxf(fmaf(v, s_sc[ic], s_sh[ic]), 0.0f);
        a0 = fmaf(v, s_w[ic],        a0);
        a1 = fmaf(v, s_w[CIN+ic],    a1);
        a2 = fmaf(v, s_w[2*CIN+ic],  a2);
    }
    float r0 = base[(b*3+0)*HW + p] + a0;
    float r1 = base[(b*3+1)*HW + p] + a1;
    float r2 = base[(b*3+2)*HW + p] + a2;
    dout[(b*3+0)*HW + p] = r0;
    dout[(b*3+1)*HW + p] = r1;
    dout[(b*3+2)*HW + p] = r2;
    if (dup) {
        dup[(b*3+0)*HW + p] = r0;
        dup[(b*3+1)*HW + p] = r1;
        dup[(b*3+2)*HW + p] = r2;
    }
}

__global__ void upsample_kernel(const float* __restrict__ src3, float* __restrict__ dst3) {
    int idx = blockIdx.x*256 + threadIdx.x;
    if (idx >= B_*3*HWF) return;
    int p = idx % HWF; int c = (idx / HWF) % 3; int b = idx / (HWF*3);
    int wo = p & 127, ho = p >> 7;
    float sx = wo*0.5f - 0.25f, sy = ho*0.5f - 0.25f;
    float x0f = floorf(sx), y0f = floorf(sy);
    float wx = sx - x0f, wy = sy - y0f;
    int x0 = (int)x0f, y0 = (int)y0f;
    int x0c = min(max(x0, 0), 63),   x1c = min(max(x0+1, 0), 63);
    int y0c = min(max(y0, 0), 63),   y1c = min(max(y0+1, 0), 63);
    const float* s = src3 + (size_t)(b*3 + c)*HWC;
    float v = s[y0c*64+x0c]*(1-wx)*(1-wy) + s[y0c*64+x1c]*wx*(1-wy)
            + s[y1c*64+x0c]*(1-wx)*wy     + s[y1c*64+x1c]*wx*wy;
    dst3[idx] = v;
}

// ---------------- host driver ----------------
extern "C" void kernel_launch(void* const* d_in, const int* in_sizes, int n_in,
                              void* d_out, int out_size) {
    const float* f0c = (const float*)d_in[0];
    const float* f1c = (const float*)d_in[1];
    const float* f0f = (const float*)d_in[2];
    const float* f1f = (const float*)d_in[3];
    const float* cw1 = (const float*)d_in[4];
    const float* cw2 = (const float*)d_in[5];
    const float* cw3 = (const float*)d_in[6];
    const float* cw4 = (const float*)d_in[7];
    const float* cw5 = (const float*)d_in[8];
    const float* cb5 = (const float*)d_in[9];
    const float* fw1 = (const float*)d_in[10];
    const float* fw2 = (const float*)d_in[11];
    const float* fw3 = (const float*)d_in[12];
    const float* fw4 = (const float*)d_in[13];
    const float* fw5 = (const float*)d_in[14];
    const float* fb5 = (const float*)d_in[15];

    float *p_cm0, *p_w1c, *p_xin, *p_c0, *p_c1, *p_cm, *p_up, *p_w1f, *p_yin, *p_f0, *p_f1;
    u16 *p_wHi, *p_wLo;
    cudaGetSymbolAddress((void**)&p_cm0, g_cm0);
    cudaGetSymbolAddress((void**)&p_w1c, g_warped1c);
    cudaGetSymbolAddress((void**)&p_xin, g_xin);
    cudaGetSymbolAddress((void**)&p_c0,  g_cbuf0);
    cudaGetSymbolAddress((void**)&p_c1,  g_cbuf1);
    cudaGetSymbolAddress((void**)&p_cm,  g_cm);
    cudaGetSymbolAddress((void**)&p_up,  g_up);
    cudaGetSymbolAddress((void**)&p_w1f, g_warped1f);
    cudaGetSymbolAddress((void**)&p_yin, g_yin);
    cudaGetSymbolAddress((void**)&p_f0,  g_fbuf0);
    cudaGetSymbolAddress((void**)&p_f1,  g_fbuf1);
    cudaGetSymbolAddress((void**)&p_wHi, g_wHi);
    cudaGetSymbolAddress((void**)&p_wLo, g_wLo);

    // smem: coarse (POS=264)*72*4 + 128*72*4 = 112896 ; fine (POS=390)*72*4 + 64*72*4 = 130752
    const int SMC = 264*72*4 + 128*72*4;
    const int SMF = 390*72*4 + 64*72*4;
    cudaFuncSetAttribute(conv_wmma_kernel<4>, cudaFuncAttributeMaxDynamicSharedMemorySize, SMC);
    cudaFuncSetAttribute(conv_wmma_kernel<2>, cudaFuncAttributeMaxDynamicSharedMemorySize, SMF);

    // weight transforms: [tap][oc][icp] split bf16
    const size_t oCW1 = 0, oCW2 = 442368, oCW3 = 1032192, oCW4 = 1622016;
    const size_t oFW1 = 2211840, oFW2 = 2248704, oFW3 = 2285568, oFW4 = 2322432;
    wtransform_kernel<<<(9*256*192+255)/256, 256>>>(cw1, p_wHi+oCW1, p_wLo+oCW1, 130, 192, 256);
    wtransform_kernel<<<(9*256*256+255)/256, 256>>>(cw2, p_wHi+oCW2, p_wLo+oCW2, 256, 256, 256);
    wtransform_kernel<<<(9*256*256+255)/256, 256>>>(cw3, p_wHi+oCW3, p_wLo+oCW3, 256, 256, 256);
    wtransform_kernel<<<(9*256*256+255)/256, 256>>>(cw4, p_wHi+oCW4, p_wLo+oCW4, 256, 256, 256);
    wtransform_kernel<<<(9*64*64+255)/256, 256>>>(fw1, p_wHi+oFW1, p_wLo+oFW1, 50, 64, 64);
    wtransform_kernel<<<(9*64*64+255)/256, 256>>>(fw2, p_wHi+oFW2, p_wLo+oFW2, 64, 64, 64);
    wtransform_kernel<<<(9*64*64+255)/256, 256>>>(fw3, p_wHi+oFW3, p_wLo+oFW3, 64, 64, 64);
    wtransform_kernel<<<(9*64*64+255)/256, 256>>>(fw4, p_wHi+oFW4, p_wLo+oFW4, 64, 64, 64);

    // coarse path
    attention_kernel<<<dim3(64, B_), 256>>>(f0c, f1c);
    gridsample_kernel<<<(B_*64*HWC)/256, 256>>>(f1c, p_cm0, p_w1c, 64, 64, 64);
    concat_c_kernel<<<(B_*130*HWC + 255)/256, 256>>>(f0c);
    conv_wmma_kernel<4><<<dim3(32, 2, B_), 256, SMC>>>(p_xin, p_wHi+oCW1, p_wLo+oCW1, p_c0, 64, 64, 130, 192, 256, 0);
    bnstats_kernel<<<256, 256>>>(p_c0, 256, HWC);
    conv_wmma_kernel<4><<<dim3(32, 2, B_), 256, SMC>>>(p_c0, p_wHi+oCW2, p_wLo+oCW2, p_c1, 64, 64, 256, 256, 256, 1);
    bnstats_kernel<<<256, 256>>>(p_c1, 256, HWC);
    conv_wmma_kernel<4><<<dim3(32, 2, B_), 256, SMC>>>(p_c1, p_wHi+oCW3, p_wLo+oCW3, p_c0, 64, 64, 256, 256, 256, 1);
    bnstats_kernel<<<256, 256>>>(p_c0, 256, HWC);
    conv_wmma_kernel<4><<<dim3(32, 2, B_), 256, SMC>>>(p_c0, p_wHi+oCW4, p_wLo+oCW4, p_c1, 64, 64, 256, 256, 256, 1);
    bnstats_kernel<<<256, 256>>>(p_c1, 256, HWC);
    conv1x1_kernel<<<(B_*HWC)/256, 256>>>(p_c1, cw5, cb5, p_cm0, (float*)d_out, p_cm, 256, HWC);

    // fine path
    upsample_kernel<<<(B_*3*HWF)/256, 256>>>(p_cm, p_up);
    gridsample_kernel<<<(B_*24*HWF)/256, 256>>>(f1f, p_up, p_w1f, 24, 128, 128);
    concat_f_kernel<<<(B_*50*HWF + 255)/256, 256>>>(f0f);
    conv_wmma_kernel<2><<<dim3(128, 1, B_), 256, SMF>>>(p_yin, p_wHi+oFW1, p_wLo+oFW1, p_f0, 128, 128, 50, 64, 64, 0);
    bnstats_kernel<<<64, 256>>>(p_f0, 64, HWF);
    conv_wmma_kernel<2><<<dim3(128, 1, B_), 256, SMF>>>(p_f0, p_wHi+oFW2, p_wLo+oFW2, p_f1, 128, 128, 64, 64, 64, 1);
    bnstats_kernel<<<64, 256>>>(p_f1, 64, HWF);
    conv_wmma_kernel<2><<<dim3(128, 1, B_), 256, SMF>>>(p_f1, p_wHi+oFW3, p_wLo+oFW3, p_f0, 128, 128, 64, 64, 64, 1);
    bnstats_kernel<<<64, 256>>>(p_f0, 64, HWF);
    conv_wmma_kernel<2><<<dim3(128, 1, B_), 256, SMF>>>(p_f0, p_wHi+oFW4, p_wLo+oFW4, p_f1, 128, 128, 64, 64, 64, 1);
    bnstats_kernel<<<64, 256>>>(p_f1, 64, HWF);
    conv1x1_kernel<<<(B_*HWF)/256, 256>>>(p_f1, fw5, fb5, p_up,
                                          (float*)d_out + B_*3*HWC, (float*)0, 64, HWF);
}

// round 8
// speedup vs baseline: 1.0318x; 1.0318x over previous
#include <cuda_runtime.h>
#include <math.h>

#define B_  4
#define HWC 4096    // 64*64
#define HWF 16384   // 128*128

typedef unsigned long long ull;

__device__ __forceinline__ ull pk2(float a, float b) {
    ull r; asm("mov.b64 %0, {%1,%2};" : "=l"(r) : "f"(a), "f"(b)); return r;
}
__device__ __forceinline__ ull fma2(ull a, ull b, ull c) {
    ull d; asm("fma.rn.f32x2 %0, %1, %2, %3;" : "=l"(d) : "l"(a), "l"(b), "l"(c)); return d;
}
__device__ __forceinline__ void unpk2(ull v, float& lo, float& hi) {
    asm("mov.b64 {%0,%1}, %2;" : "=f"(lo), "=f"(hi) : "l"(v));
}

// ---------------- scratch ----------------
__device__ float g_cm0[B_*3*HWC];
__device__ float g_warped1c[B_*64*HWC];
__device__ float g_cbuf0[B_*256*HWC];
__device__ float g_cbuf1[B_*256*HWC];
__device__ float g_cm[B_*3*HWC];
__device__ float g_up[B_*3*HWF];
__device__ float g_warped1f[B_*24*HWF];
__device__ float g_fbuf0[B_*64*HWF];
__device__ float g_fbuf1[B_*64*HWF];
__device__ float g_bnscale[256];
__device__ float g_bnshift[256];

// profiling alignment: 5 no-ops so ncu (-s 5 -c 1) captures the attention kernel
__global__ void noop_kernel() {}

// ---------------- fused correlation + softmax + expected-position ----------------
// block = (2 rows, batch): 128 queries, 4096 keys, D=64, V = analytic pos grid.
// 256 threads = 32 q-groups(4q) x 8 k-lanes(8k). Scale folded into Q fill; gy constant
// per key tile; K prefetched through registers; final merge via warp shuffles.
__global__ __launch_bounds__(256)
void attention_kernel(const float* __restrict__ f0, const float* __restrict__ f1) {
    __shared__ float q_s[64][128];
    __shared__ float k_s[64][64];
    int b = blockIdx.y, h2 = blockIdx.x;
    int tid = threadIdx.x;
    int tq = tid >> 3, tk = tid & 7;
    const float* f0b = f0 + (size_t)b*64*HWC + h2*128;
    const float* f1b = f1 + (size_t)b*64*HWC;

    // Q fill (scaled by 1/sqrt(64))
    for (int i4 = tid; i4 < 2048; i4 += 256) {
        int c = i4 >> 5, jo = (i4 & 31) * 4;
        float4 v = *(const float4*)&f0b[c*HWC + jo];
        v.x *= 0.125f; v.y *= 0.125f; v.z *= 0.125f; v.w *= 0.125f;
        *(float4*)&q_s[c][jo] = v;
    }

    float gxr[8];
#pragma unroll
    for (int j = 0; j < 8; j++)
        gxr[j] = (float)(2*(tk*8 + j) + 1) * (1.0f/64.0f) - 1.0f;

    float m[4], ss[4], px[4], py[4];
#pragma unroll
    for (int i = 0; i < 4; i++) { m[i] = -1e30f; ss[i] = 0.f; px[i] = 0.f; py[i] = 0.f; }

    // K prefetch (t=0)
    float4 kr[4];
#pragma unroll
    for (int k = 0; k < 4; k++) {
        int i4 = tid + k*256;
        kr[k] = *(const float4*)&f1b[(size_t)(i4 >> 4)*HWC + (i4 & 15)*4];
    }

    for (int t = 0; t < 64; ++t) {
        __syncthreads();
#pragma unroll
        for (int k = 0; k < 4; k++) {
            int i4 = tid + k*256;
            *(float4*)&k_s[i4 >> 4][(i4 & 15)*4] = kr[k];
        }
        __syncthreads();
        if (t < 63) {
#pragma unroll
            for (int k = 0; k < 4; k++) {
                int i4 = tid + k*256;
                kr[k] = *(const float4*)&f1b[(size_t)(i4 >> 4)*HWC + (t+1)*64 + (i4 & 15)*4];
            }
        }
        ull acc[4][4];
#pragma unroll
        for (int i = 0; i < 4; i++)
#pragma unroll
            for (int j = 0; j < 4; j++) acc[i][j] = 0ull;
#pragma unroll 8
        for (int c = 0; c < 64; ++c) {
            const ull* kp = (const ull*)&k_s[c][tk*8];
            ull k0 = kp[0], k1 = kp[1], k2 = kp[2], k3 = kp[3];
#pragma unroll
            for (int i = 0; i < 4; i++) {
                float q = q_s[c][tq*4 + i];
                ull qq = pk2(q, q);
                acc[i][0] = fma2(qq, k0, acc[i][0]);
                acc[i][1] = fma2(qq, k1, acc[i][1]);
                acc[i][2] = fma2(qq, k2, acc[i][2]);
                acc[i][3] = fma2(qq, k3, acc[i][3]);
            }
        }
        float gy = (float)(2*t + 1) * (1.0f/64.0f) - 1.0f;
#pragma unroll
        for (int i = 0; i < 4; i++) {
            float sc[8];
            unpk2(acc[i][0], sc[0], sc[1]);
            unpk2(acc[i][1], sc[2], sc[3]);
            unpk2(acc[i][2], sc[4], sc[5]);
            unpk2(acc[i][3], sc[6], sc[7]);
            float mt = m[i];
#pragma unroll
            for (int j = 0; j < 8; j++) mt = fmaxf(mt, sc[j]);
            float f = __expf(m[i] - mt);
            float es = 0.f, ex = 0.f;
#pragma unroll
            for (int j = 0; j < 8; j++) {
                float e = __expf(sc[j] - mt);
                es += e;
                ex = fmaf(e, gxr[j], ex);
            }
            ss[i] = fmaf(ss[i], f, es);
            px[i] = fmaf(px[i], f, ex);
            py[i] = fmaf(py[i], f, gy*es);
            m[i] = mt;
        }
    }

    // merge across the 8 k-lanes via shuffles (lanes differ in bits 0..2)
#pragma unroll
    for (int d = 1; d < 8; d <<= 1) {
#pragma unroll
        for (int i = 0; i < 4; i++) {
            float mo  = __shfl_xor_sync(0xFFFFFFFF, m[i],  d);
            float sso = __shfl_xor_sync(0xFFFFFFFF, ss[i], d);
            float pxo = __shfl_xor_sync(0xFFFFFFFF, px[i], d);
            float pyo = __shfl_xor_sync(0xFFFFFFFF, py[i], d);
            float M = fmaxf(m[i], mo);
            float fa = __expf(m[i] - M), fb = __expf(mo - M);
            ss[i] = ss[i]*fa + sso*fb;
            px[i] = px[i]*fa + pxo*fb;
            py[i] = py[i]*fa + pyo*fb;
            m[i] = M;
        }
    }
    if (tk == 0) {
#pragma unroll
        for (int i = 0; i < 4; i++) {
            int p = h2*128 + tq*4 + i;
            float inv = 1.0f / ss[i];
            g_cm0[(b*3+0)*HWC + p] = px[i] * inv;
            g_cm0[(b*3+1)*HWC + p] = py[i] * inv;
            g_cm0[(b*3+2)*HWC + p] = 0.0f;
        }
    }
}

// ---------------- bilinear grid-sample ----------------
__global__ void gridsample_kernel(const float* __restrict__ img, const float* __restrict__ cm,
                                  float* __restrict__ out, int C, int H, int W) {
    int idx = blockIdx.x*256 + threadIdx.x;
    int HW = H*W;
    int total = B_*C*HW;
    if (idx >= total) return;
    int p = idx % HW; int c = (idx / HW) % C; int b = idx / (HW*C);
    float gx = cm[(b*3+0)*HW + p];
    float gy = cm[(b*3+1)*HW + p];
    float x = (gx + 1.0f)*(W*0.5f) - 0.5f;
    float y = (gy + 1.0f)*(H*0.5f) - 0.5f;
    float x0f = floorf(x), y0f = floorf(y);
    float wx = x - x0f, wy = y - y0f;
    int x0 = (int)x0f, y0 = (int)y0f;
    const float* im = img + (size_t)(b*C + c)*HW;
    float v[4];
#pragma unroll
    for (int iy = 0; iy < 2; iy++)
#pragma unroll
        for (int ix = 0; ix < 2; ix++) {
            int xi = x0 + ix, yi = y0 + iy;
            bool valid = (xi >= 0 && xi < W && yi >= 0 && yi < H);
            int xc = min(max(xi, 0), W-1), yc = min(max(yi, 0), H-1);
            v[iy*2+ix] = valid ? im[yc*W + xc] : 0.0f;
        }
    out[idx] = v[0]*(1-wx)*(1-wy) + v[1]*wx*(1-wy) + v[2]*(1-wx)*wy + v[3]*wx*wy;
}

// ---------------- direct 3x3 conv, SAME, packed f32x2, multi-source input ---------------
// Input channels come from up to 3 concatenated sources (fuses the concat kernels):
// c in [0,C0): in0 (S0 stored ch/batch); [C0,C0+C1): in1; rest: in2.
__global__ __launch_bounds__(256, 2)
void conv3x3_kernel(const float* __restrict__ in0, int S0, int C0,
                    const float* __restrict__ in1, int S1, int C1,
                    const float* __restrict__ in2, int S2,
                    const float* __restrict__ wgt, float* __restrict__ out,
                    int CIN, int COUT, int H, int W, int applyBn) {
    int b = blockIdx.z;
    int oc0 = blockIdx.y * 64;
    int tilesW = W >> 4;
    int th0 = (blockIdx.x / tilesW) * 16;
    int tw0 = (blockIdx.x % tilesW) * 16;
    int tid = threadIdx.x;
    int wrp = tid >> 5, ln = tid & 31;
    int hl = ln >> 1;
    int seg = (ln & 1) * 8;
    int HW = H*W;

    __shared__ __align__(16) float s_in[8][18][20];
    __shared__ __align__(16) float s_w[8][9][64];

    ull acc[4][8];
#pragma unroll
    for (int o2 = 0; o2 < 4; o2++)
#pragma unroll
        for (int j = 0; j < 8; j++) acc[o2][j] = 0ull;

    int nChunks = (CIN + 7) >> 3;
    for (int ch = 0; ch < nChunks; ++ch) {
        int ic0 = ch * 8;
        __syncthreads();
        for (int idx = tid; idx < 8*18*18; idx += 256) {
            int ic = idx / 324; int rem = idx % 324;
            int r = rem / 18, c = rem % 18;
            int gh = th0 + r - 1, gw = tw0 + c - 1;
            int icg = ic0 + ic;
            float v = 0.0f;
            if (icg < CIN && gh >= 0 && gh < H && gw >= 0 && gw < W) {
                const float* src; int cc;
                if (icg < C0)            { src = in0 + (size_t)b*S0*HW; cc = icg; }
                else if (icg < C0 + C1)  { src = in1 + (size_t)b*S1*HW; cc = icg - C0; }
                else                     { src = in2 + (size_t)b*S2*HW; cc = icg - C0 - C1; }
                v = src[(size_t)cc*HW + gh*W + gw];
                if (applyBn) v = fmaxf(fmaf(v, g_bnscale[icg], g_bnshift[icg]), 0.0f);
            }
            s_in[ic][r][c] = v;
        }
        for (int idx = tid; idx < 8*9*64; idx += 256) {
            int ic = idx / 576; int k = (idx / 64) % 9; int oc = idx & 63;
            int icg = ic0 + ic;
            s_w[ic][k][oc] = (icg < CIN) ? wgt[((size_t)(oc0+oc)*CIN + icg)*9 + k] : 0.0f;
        }
        __syncthreads();

        for (int ic = 0; ic < 8; ++ic) {
#pragma unroll
            for (int kh = 0; kh < 3; ++kh) {
                const float* rp = &s_in[ic][hl + kh][seg];
                float4 a0 = *(const float4*)rp;
                float4 a1 = *(const float4*)(rp + 4);
                float v8 = rp[8], v9 = rp[9];
                ull vv[10];
                vv[0] = pk2(a0.x, a0.x); vv[1] = pk2(a0.y, a0.y);
                vv[2] = pk2(a0.z, a0.z); vv[3] = pk2(a0.w, a0.w);
                vv[4] = pk2(a1.x, a1.x); vv[5] = pk2(a1.y, a1.y);
                vv[6] = pk2(a1.z, a1.z); vv[7] = pk2(a1.w, a1.w);
                vv[8] = pk2(v8, v8);     vv[9] = pk2(v9, v9);
#pragma unroll
                for (int kw = 0; kw < 3; ++kw) {
                    const ull* wp = (const ull*)&s_w[ic][kh*3 + kw][wrp*8];
#pragma unroll
                    for (int o2 = 0; o2 < 4; ++o2) {
                        ull w2 = wp[o2];
#pragma unroll
                        for (int j = 0; j < 8; ++j)
                            acc[o2][j] = fma2(w2, vv[kw + j], acc[o2][j]);
                    }
                }
            }
        }
    }
    int orow = th0 + hl;
#pragma unroll
    for (int o2 = 0; o2 < 4; ++o2) {
        int oc = oc0 + wrp*8 + o2*2;
        float* p0 = &out[((size_t)(b*COUT + oc  )*H + orow)*W + tw0 + seg];
        float* p1 = &out[((size_t)(b*COUT + oc+1)*H + orow)*W + tw0 + seg];
#pragma unroll
        for (int j = 0; j < 8; ++j) {
            float lo, hi; unpk2(acc[o2][j], lo, hi);
            p0[j] = lo; p1[j] = hi;
        }
    }
}

// ---------------- per-channel batch stats -> scale/shift ----------------
__global__ void bnstats_kernel(const float* __restrict__ in, int C, int HW) {
    int c = blockIdx.x;
    int tid = threadIdx.x;
    float s = 0.f, s2 = 0.f;
    for (int b = 0; b < B_; ++b) {
        const float* p = in + (size_t)(b*C + c)*HW;
        for (int i = tid; i < HW; i += 256) { float v = p[i]; s += v; s2 += v*v; }
    }
    __shared__ float sh[256], sh2[256];
    sh[tid] = s; sh2[tid] = s2;
    __syncthreads();
    for (int o = 128; o > 0; o >>= 1) {
        if (tid < o) { sh[tid] += sh[tid+o]; sh2[tid] += sh2[tid+o]; }
        __syncthreads();
    }
    if (tid == 0) {
        float n = (float)(B_*HW);
        float mean = sh[0] / n;
        float var  = sh2[0] / n - mean*mean;
        float sc = rsqrtf(var + 1e-5f);
        g_bnscale[c] = sc;
        g_bnshift[c] = -mean * sc;
    }
}

// ---------------- 1x1 conv head ----------------
__global__ void conv1x1_kernel(const float* __restrict__ inbuf, const float* __restrict__ wgt,
                               const float* __restrict__ bias, const float* __restrict__ base,
                               float* __restrict__ dout, float* __restrict__ dup,
                               int CIN, int HW) {
    __shared__ float s_w[3*256], s_sc[256], s_sh[256];
    int tid = threadIdx.x;
    for (int i = tid; i < 3*CIN; i += 256) s_w[i] = wgt[i];
    for (int i = tid; i < CIN; i += 256) { s_sc[i] = g_bnscale[i]; s_sh[i] = g_bnshift[i]; }
    __syncthreads();
    int idx = blockIdx.x*256 + tid;
    int p = idx % HW, b = idx / HW;
    float a0 = bias[0], a1 = bias[1], a2 = bias[2];
    const float* ip = inbuf + (size_t)b*CIN*HW + p;
    for (int ic = 0; ic < CIN; ++ic) {
        float v = ip[(size_t)ic*HW];
        v = fmaxf(fmaf(v, s_sc[ic], s_sh[ic]), 0.0f);
        a0 = fmaf(v, s_w[ic],        a0);
        a1 = fmaf(v, s_w[CIN+ic],    a1);
        a2 = fmaf(v, s_w[2*CIN+ic],  a2);
    }
    float r0 = base[(b*3+0)*HW + p] + a0;
    float r1 = base[(b*3+1)*HW + p] + a1;
    float r2 = base[(b*3+2)*HW + p] + a2;
    dout[(b*3+0)*HW + p] = r0;
    dout[(b*3+1)*HW + p] = r1;
    dout[(b*3+2)*HW + p] = r2;
    if (dup) {
        dup[(b*3+0)*HW + p] = r0;
        dup[(b*3+1)*HW + p] = r1;
        dup[(b*3+2)*HW + p] = r2;
    }
}

// ---------------- 2x bilinear upsample ----------------
__global__ void upsample_kernel(const float* __restrict__ src3, float* __restrict__ dst3) {
    int idx = blockIdx.x*256 + threadIdx.x;
    if (idx >= B_*3*HWF) return;
    int p = idx % HWF; int c = (idx / HWF) % 3; int b = idx / (HWF*3);
    int wo = p & 127, ho = p >> 7;
    float sx = wo*0.5f - 0.25f, sy = ho*0.5f - 0.25f;
    float x0f = floorf(sx), y0f = floorf(sy);
    float wx = sx - x0f, wy = sy - y0f;
    int x0 = (int)x0f, y0 = (int)y0f;
    int x0c = min(max(x0, 0), 63),   x1c = min(max(x0+1, 0), 63);
    int y0c = min(max(y0, 0), 63),   y1c = min(max(y0+1, 0), 63);
    const float* s = src3 + (size_t)(b*3 + c)*HWC;
    float v = s[y0c*64+x0c]*(1-wx)*(1-wy) + s[y0c*64+x1c]*wx*(1-wy)
            + s[y1c*64+x0c]*(1-wx)*wy     + s[y1c*64+x1c]*wx*wy;
    dst3[idx] = v;
}

// ---------------- host driver ----------------
extern "C" void kernel_launch(void* const* d_in, const int* in_sizes, int n_in,
                              void* d_out, int out_size) {
    const float* f0c = (const float*)d_in[0];
    const float* f1c = (const float*)d_in[1];
    const float* f0f = (const float*)d_in[2];
    const float* f1f = (const float*)d_in[3];
    const float* cw1 = (const float*)d_in[4];
    const float* cw2 = (const float*)d_in[5];
    const float* cw3 = (const float*)d_in[6];
    const float* cw4 = (const float*)d_in[7];
    const float* cw5 = (const float*)d_in[8];
    const float* cb5 = (const float*)d_in[9];
    const float* fw1 = (const float*)d_in[10];
    const float* fw2 = (const float*)d_in[11];
    const float* fw3 = (const float*)d_in[12];
    const float* fw4 = (const float*)d_in[13];
    const float* fw5 = (const float*)d_in[14];
    const float* fb5 = (const float*)d_in[15];

    float *p_cm0, *p_w1c, *p_c0, *p_c1, *p_cm, *p_up, *p_w1f, *p_f0, *p_f1;
    cudaGetSymbolAddress((void**)&p_cm0, g_cm0);
    cudaGetSymbolAddress((void**)&p_w1c, g_warped1c);
    cudaGetSymbolAddress((void**)&p_c0,  g_cbuf0);
    cudaGetSymbolAddress((void**)&p_c1,  g_cbuf1);
    cudaGetSymbolAddress((void**)&p_cm,  g_cm);
    cudaGetSymbolAddress((void**)&p_up,  g_up);
    cudaGetSymbolAddress((void**)&p_w1f, g_warped1f);
    cudaGetSymbolAddress((void**)&p_f0,  g_fbuf0);
    cudaGetSymbolAddress((void**)&p_f1,  g_fbuf1);

    // launches 1-5: no-ops so ncu (-s 5 -c 1) profiles attention at launch 6
    for (int i = 0; i < 5; i++) noop_kernel<<<1, 32>>>();

    // coarse path
    attention_kernel<<<dim3(32, B_), 256>>>(f0c, f1c);
    gridsample_kernel<<<(B_*64*HWC)/256, 256>>>(f1c, p_cm0, p_w1c, 64, 64, 64);
    conv3x3_kernel<<<dim3(16, 4, B_), 256>>>(f0c, 64, 64, p_w1c, 64, 64, p_cm0, 3,
                                             cw1, p_c0, 130, 256, 64, 64, 0);
    bnstats_kernel<<<256, 256>>>(p_c0, 256, HWC);
    conv3x3_kernel<<<dim3(16, 4, B_), 256>>>(p_c0, 256, 256, p_c0, 256, 0, p_c0, 256,
                                             cw2, p_c1, 256, 256, 64, 64, 1);
    bnstats_kernel<<<256, 256>>>(p_c1, 256, HWC);
    conv3x3_kernel<<<dim3(16, 4, B_), 256>>>(p_c1, 256, 256, p_c1, 256, 0, p_c1, 256,
                                             cw3, p_c0, 256, 256, 64, 64, 1);
    bnstats_kernel<<<256, 256>>>(p_c0, 256, HWC);
    conv3x3_kernel<<<dim3(16, 4, B_), 256>>>(p_c0, 256, 256, p_c0, 256, 0, p_c0, 256,
                                             cw4, p_c1, 256, 256, 64, 64, 1);
    bnstats_kernel<<<256, 256>>>(p_c1, 256, HWC);
    conv1x1_kernel<<<(B_*HWC)/256, 256>>>(p_c1, cw5, cb5, p_cm0, (float*)d_out, p_cm, 256, HWC);

    // fine path
    upsample_kernel<<<(B_*3*HWF)/256, 256>>>(p_cm, p_up);
    gridsample_kernel<<<(B_*24*HWF)/256, 256>>>(f1f, p_up, p_w1f, 24, 128, 128);
    conv3x3_kernel<<<dim3(64, 1, B_), 256>>>(f0f, 24, 24, p_w1f, 24, 24, p_up, 3,
                                             fw1, p_f0, 50, 64, 128, 128, 0);
    bnstats_kernel<<<64, 256>>>(p_f0, 64, HWF);
    conv3x3_kernel<<<dim3(64, 1, B_), 256>>>(p_f0, 64, 64, p_f0, 64, 0, p_f0, 64,
                                             fw2, p_f1, 64, 64, 128, 128, 1);
    bnstats_kernel<<<64, 256>>>(p_f1, 64, HWF);
    conv3x3_kernel<<<dim3(64, 1, B_), 256>>>(p_f1, 64, 64, p_f1, 64, 0, p_f1, 64,
                                             fw3, p_f0, 64, 64, 128, 128, 1);
    bnstats_kernel<<<64, 256>>>(p_f0, 64, HWF);
    conv3x3_kernel<<<dim3(64, 1, B_), 256>>>(p_f0, 64, 64, p_f0, 64, 0, p_f0, 64,
                                             fw4, p_f1, 64, 64, 128, 128, 1);
    bnstats_kernel<<<64, 256>>>(p_f1, 64, HWF);
    conv1x1_kernel<<<(B_*HWF)/256, 256>>>(p_f1, fw5, fb5, p_up,
                                          (float*)d_out + B_*3*HWC, (float*)0, 64, HWF);
}

// round 9
// speedup vs baseline: 1.0862x; 1.0527x over previous
#include <cuda_runtime.h>
#include <math.h>

#define B_  4
#define HWC 4096    // 64*64
#define HWF 16384   // 128*128

typedef unsigned long long ull;

__device__ __forceinline__ ull pk2(float a, float b) {
    ull r; asm("mov.b64 %0, {%1,%2};" : "=l"(r) : "f"(a), "f"(b)); return r;
}
__device__ __forceinline__ ull fma2(ull a, ull b, ull c) {
    ull d; asm("fma.rn.f32x2 %0, %1, %2, %3;" : "=l"(d) : "l"(a), "l"(b), "l"(c)); return d;
}
__device__ __forceinline__ ull add2(ull a, ull b) {
    ull d; asm("add.rn.f32x2 %0, %1, %2;" : "=l"(d) : "l"(a), "l"(b)); return d;
}
__device__ __forceinline__ void unpk2(ull v, float& lo, float& hi) {
    asm("mov.b64 {%0,%1}, %2;" : "=f"(lo), "=f"(hi) : "l"(v));
}

// ---------------- scratch ----------------
__device__ float g_cm0[B_*3*HWC];
__device__ float g_warped1c[B_*64*HWC];
__device__ float g_cbuf0[B_*256*HWC];
__device__ float g_cbuf1[B_*256*HWC];
__device__ float g_cm[B_*3*HWC];
__device__ float g_up[B_*3*HWF];
__device__ float g_warped1f[B_*24*HWF];
__device__ float g_fbuf0[B_*64*HWF];
__device__ float g_fbuf1[B_*64*HWF];
__device__ float g_pv [256*256];    // per-(oc, block) partial sums
__device__ float g_pv2[256*256];    // per-(oc, block) partial sum of squares
__device__ float g_bnS[8*256];      // per-layer BN scale
__device__ float g_bnH[8*256];      // per-layer BN shift

// ---------------- fused correlation + softmax + expected-position ----------------
// block = (row, batch): 64 queries, 4096 keys, D=64, V = analytic pos grid.
// 256 threads = 16 q-groups(4q) x 16 k-lanes(4k). Scale folded into Q fill; gx in regs;
// gy constant per key tile; K register-prefetched; merge via warp shuffles (tk = 4 lane bits).
__global__ __launch_bounds__(256)
void attention_kernel(const float* __restrict__ f0, const float* __restrict__ f1) {
    __shared__ float q_s[64][68];
    __shared__ float k_s[64][68];
    int b = blockIdx.y, h = blockIdx.x;
    int tid = threadIdx.x;
    int tq = tid >> 4, tk = tid & 15;
    const float* f0b = f0 + (size_t)b*64*HWC;
    const float* f1b = f1 + (size_t)b*64*HWC;

    for (int idx = tid; idx < 4096; idx += 256) {
        int c = idx >> 6, q = idx & 63;
        q_s[c][q] = f0b[c*HWC + h*64 + q] * 0.125f;
    }

    float gxr[4];
#pragma unroll
    for (int j = 0; j < 4; j++)
        gxr[j] = (float)(2*(tk*4 + j) + 1) * (1.0f/64.0f) - 1.0f;

    float m[4], ss[4], px[4], py[4];
#pragma unroll
    for (int i = 0; i < 4; i++) { m[i] = -1e30f; ss[i] = 0.f; px[i] = 0.f; py[i] = 0.f; }

    // K prefetch (t=0): 16 floats/thread
    float4 kr[4];
#pragma unroll
    for (int k = 0; k < 4; k++) {
        int i4 = tid + k*256;
        kr[k] = *(const float4*)&f1b[(size_t)(i4 >> 4)*HWC + (i4 & 15)*4];
    }

    for (int t = 0; t < 64; ++t) {
        __syncthreads();
#pragma unroll
        for (int k = 0; k < 4; k++) {
            int i4 = tid + k*256;
            *(float4*)&k_s[i4 >> 4][(i4 & 15)*4] = kr[k];
        }
        __syncthreads();
        if (t < 63) {
#pragma unroll
            for (int k = 0; k < 4; k++) {
                int i4 = tid + k*256;
                kr[k] = *(const float4*)&f1b[(size_t)(i4 >> 4)*HWC + (t+1)*64 + (i4 & 15)*4];
            }
        }
        ull acc[4][2];
#pragma unroll
        for (int i = 0; i < 4; i++) { acc[i][0] = 0ull; acc[i][1] = 0ull; }
#pragma unroll 8
        for (int c = 0; c < 64; ++c) {
            const ull* kp = (const ull*)&k_s[c][tk*4];
            ull k01 = kp[0], k23 = kp[1];
#pragma unroll
            for (int i = 0; i < 4; i++) {
                float q = q_s[c][tq*4 + i];
                ull qq = pk2(q, q);
                acc[i][0] = fma2(qq, k01, acc[i][0]);
                acc[i][1] = fma2(qq, k23, acc[i][1]);
            }
        }
        float gy = (float)(2*t + 1) * (1.0f/64.0f) - 1.0f;
#pragma unroll
        for (int i = 0; i < 4; i++) {
            float sc[4];
            unpk2(acc[i][0], sc[0], sc[1]);
            unpk2(acc[i][1], sc[2], sc[3]);
            float mt = m[i];
#pragma unroll
            for (int j = 0; j < 4; j++) mt = fmaxf(mt, sc[j]);
            float f = __expf(m[i] - mt);
            float es = 0.f, ex = 0.f;
#pragma unroll
            for (int j = 0; j < 4; j++) {
                float e = __expf(sc[j] - mt);
                es += e;
                ex = fmaf(e, gxr[j], ex);
            }
            ss[i] = fmaf(ss[i], f, es);
            px[i] = fmaf(px[i], f, ex);
            py[i] = fmaf(py[i], f, gy*es);
            m[i] = mt;
        }
    }

    // merge across 16 k-lanes (lane bits 0..3) via shuffles
#pragma unroll
    for (int d = 1; d < 16; d <<= 1) {
#pragma unroll
        for (int i = 0; i < 4; i++) {
            float mo  = __shfl_xor_sync(0xFFFFFFFF, m[i],  d);
            float sso = __shfl_xor_sync(0xFFFFFFFF, ss[i], d);
            float pxo = __shfl_xor_sync(0xFFFFFFFF, px[i], d);
            float pyo = __shfl_xor_sync(0xFFFFFFFF, py[i], d);
            float M = fmaxf(m[i], mo);
            float fa = __expf(m[i] - M), fb = __expf(mo - M);
            ss[i] = ss[i]*fa + sso*fb;
            px[i] = px[i]*fa + pxo*fb;
            py[i] = py[i]*fa + pyo*fb;
            m[i] = M;
        }
    }
    if (tk == 0) {
#pragma unroll
        for (int i = 0; i < 4; i++) {
            int p = h*64 + tq*4 + i;
            float inv = 1.0f / ss[i];
            g_cm0[(b*3+0)*HWC + p] = px[i] * inv;
            g_cm0[(b*3+1)*HWC + p] = py[i] * inv;
            g_cm0[(b*3+2)*HWC + p] = 0.0f;
        }
    }
}

// ---------------- bilinear grid-sample ----------------
__global__ void gridsample_kernel(const float* __restrict__ img, const float* __restrict__ cm,
                                  float* __restrict__ out, int C, int H, int W) {
    int idx = blockIdx.x*256 + threadIdx.x;
    int HW = H*W;
    int total = B_*C*HW;
    if (idx >= total) return;
    int p = idx % HW; int c = (idx / HW) % C; int b = idx / (HW*C);
    float gx = cm[(b*3+0)*HW + p];
    float gy = cm[(b*3+1)*HW + p];
    float x = (gx + 1.0f)*(W*0.5f) - 0.5f;
    float y = (gy + 1.0f)*(H*0.5f) - 0.5f;
    float x0f = floorf(x), y0f = floorf(y);
    float wx = x - x0f, wy = y - y0f;
    int x0 = (int)x0f, y0 = (int)y0f;
    const float* im = img + (size_t)(b*C + c)*HW;
    float v[4];
#pragma unroll
    for (int iy = 0; iy < 2; iy++)
#pragma unroll
        for (int ix = 0; ix < 2; ix++) {
            int xi = x0 + ix, yi = y0 + iy;
            bool valid = (xi >= 0 && xi < W && yi >= 0 && yi < H);
            int xc = min(max(xi, 0), W-1), yc = min(max(yi, 0), H-1);
            v[iy*2+ix] = valid ? im[yc*W + xc] : 0.0f;
        }
    out[idx] = v[0]*(1-wx)*(1-wy) + v[1]*wx*(1-wy) + v[2]*(1-wx)*wy + v[3]*wx*wy;
}

// ---------------- direct 3x3 conv, packed f32x2, multi-source input, BN-stat epilogue ---
__global__ __launch_bounds__(256, 2)
void conv3x3_kernel(const float* __restrict__ in0, int S0, int C0,
                    const float* __restrict__ in1, int S1, int C1,
                    const float* __restrict__ in2, int S2,
                    const float* __restrict__ wgt, float* __restrict__ out,
                    int CIN, int COUT, int H, int W,
                    const float* __restrict__ bnS, const float* __restrict__ bnH,
                    float* __restrict__ pv, float* __restrict__ pv2) {
    int b = blockIdx.z;
    int oc0 = blockIdx.y * 64;
    int tilesW = W >> 4;
    int th0 = (blockIdx.x / tilesW) * 16;
    int tw0 = (blockIdx.x % tilesW) * 16;
    int tid = threadIdx.x;
    int wrp = tid >> 5, ln = tid & 31;
    int hl = ln >> 1;
    int seg = (ln & 1) * 8;
    int HW = H*W;

    __shared__ __align__(16) float s_in[8][18][20];
    __shared__ __align__(16) float s_w[8][9][64];

    ull acc[4][8];
#pragma unroll
    for (int o2 = 0; o2 < 4; o2++)
#pragma unroll
        for (int j = 0; j < 8; j++) acc[o2][j] = 0ull;

    int nChunks = (CIN + 7) >> 3;
    for (int ch = 0; ch < nChunks; ++ch) {
        int ic0 = ch * 8;
        __syncthreads();
        for (int idx = tid; idx < 8*18*18; idx += 256) {
            int ic = idx / 324; int rem = idx % 324;
            int r = rem / 18, c = rem % 18;
            int gh = th0 + r - 1, gw = tw0 + c - 1;
            int icg = ic0 + ic;
            float v = 0.0f;
            if (icg < CIN && gh >= 0 && gh < H && gw >= 0 && gw < W) {
                const float* src; int cc;
                if (icg < C0)            { src = in0 + (size_t)b*S0*HW; cc = icg; }
                else if (icg < C0 + C1)  { src = in1 + (size_t)b*S1*HW; cc = icg - C0; }
                else                     { src = in2 + (size_t)b*S2*HW; cc = icg - C0 - C1; }
                v = src[(size_t)cc*HW + gh*W + gw];
                if (bnS) v = fmaxf(fmaf(v, bnS[icg], bnH[icg]), 0.0f);
            }
            s_in[ic][r][c] = v;
        }
        for (int idx = tid; idx < 8*9*64; idx += 256) {
            int ic = idx / 576; int k = (idx / 64) % 9; int oc = idx & 63;
            int icg = ic0 + ic;
            s_w[ic][k][oc] = (icg < CIN) ? wgt[((size_t)(oc0+oc)*CIN + icg)*9 + k] : 0.0f;
        }
        __syncthreads();

        for (int ic = 0; ic < 8; ++ic) {
#pragma unroll
            for (int kh = 0; kh < 3; ++kh) {
                const float* rp = &s_in[ic][hl + kh][seg];
                float4 a0 = *(const float4*)rp;
                float4 a1 = *(const float4*)(rp + 4);
                float v8 = rp[8], v9 = rp[9];
                ull vv[10];
                vv[0] = pk2(a0.x, a0.x); vv[1] = pk2(a0.y, a0.y);
                vv[2] = pk2(a0.z, a0.z); vv[3] = pk2(a0.w, a0.w);
                vv[4] = pk2(a1.x, a1.x); vv[5] = pk2(a1.y, a1.y);
                vv[6] = pk2(a1.z, a1.z); vv[7] = pk2(a1.w, a1.w);
                vv[8] = pk2(v8, v8);     vv[9] = pk2(v9, v9);
#pragma unroll
                for (int kw = 0; kw < 3; ++kw) {
                    const ull* wp = (const ull*)&s_w[ic][kh*3 + kw][wrp*8];
#pragma unroll
                    for (int o2 = 0; o2 < 4; ++o2) {
                        ull w2 = wp[o2];
#pragma unroll
                        for (int j = 0; j < 8; ++j)
                            acc[o2][j] = fma2(w2, vv[kw + j], acc[o2][j]);
                    }
                }
            }
        }
    }
    int orow = th0 + hl;
#pragma unroll
    for (int o2 = 0; o2 < 4; ++o2) {
        int oc = oc0 + wrp*8 + o2*2;
        float* p0 = &out[((size_t)(b*COUT + oc  )*H + orow)*W + tw0 + seg];
        float* p1 = &out[((size_t)(b*COUT + oc+1)*H + orow)*W + tw0 + seg];
#pragma unroll
        for (int j = 0; j < 8; ++j) {
            float lo, hi; unpk2(acc[o2][j], lo, hi);
            p0[j] = lo; p1[j] = hi;
        }
    }
    // BN-stat partials: per-warp sums over its 8 oc x 256 px, deterministic (no atomics)
    float vals[16];
#pragma unroll
    for (int o2 = 0; o2 < 4; ++o2) {
        ull sv = 0ull, sq = 0ull;
#pragma unroll
        for (int j = 0; j < 8; ++j) {
            sv = add2(sv, acc[o2][j]);
            sq = fma2(acc[o2][j], acc[o2][j], sq);
        }
        unpk2(sv, vals[o2*4+0], vals[o2*4+1]);
        unpk2(sq, vals[o2*4+2], vals[o2*4+3]);
    }
#pragma unroll
    for (int d = 16; d > 0; d >>= 1)
#pragma unroll
        for (int i = 0; i < 16; i++)
            vals[i] += __shfl_down_sync(0xFFFFFFFF, vals[i], d);
    if (ln == 0) {
        int slot = b * gridDim.x + blockIdx.x;
#pragma unroll
        for (int o2 = 0; o2 < 4; ++o2) {
            int oc = oc0 + wrp*8 + o2*2;
            pv [oc*256 + slot]     = vals[o2*4+0];
            pv [(oc+1)*256 + slot] = vals[o2*4+1];
            pv2[oc*256 + slot]     = vals[o2*4+2];
            pv2[(oc+1)*256 + slot] = vals[o2*4+3];
        }
    }
}

// ---------------- BN partial-sum reduction -> scale/shift ----------------
__global__ void bnreduce_kernel(const float* __restrict__ pv, const float* __restrict__ pv2,
                                int NB, float n, float* __restrict__ bnS, float* __restrict__ bnH) {
    int c = blockIdx.x;
    int tid = threadIdx.x;
    float s = 0.f, s2 = 0.f;
    if (tid < NB) { s = pv[c*256 + tid]; s2 = pv2[c*256 + tid]; }
    __shared__ float sh[8], sh2[8];
#pragma unroll
    for (int d = 16; d > 0; d >>= 1) {
        s  += __shfl_down_sync(0xFFFFFFFF, s,  d);
        s2 += __shfl_down_sync(0xFFFFFFFF, s2, d);
    }
    if ((tid & 31) == 0) { sh[tid >> 5] = s; sh2[tid >> 5] = s2; }
    __syncthreads();
    if (tid == 0) {
        float S = 0.f, S2 = 0.f;
        for (int w = 0; w < 8; w++) { S += sh[w]; S2 += sh2[w]; }
        float mean = S / n;
        float var  = S2 / n - mean*mean;
        float sc = rsqrtf(var + 1e-5f);
        bnS[c] = sc;
        bnH[c] = -mean * sc;
    }
}

// ---------------- 1x1 conv head ----------------
__global__ void conv1x1_kernel(const float* __restrict__ inbuf, const float* __restrict__ wgt,
                               const float* __restrict__ bias, const float* __restrict__ base,
                               float* __restrict__ dout, float* __restrict__ dup,
                               const float* __restrict__ bnS, const float* __restrict__ bnH,
                               int CIN, int HW) {
    __shared__ float s_w[3*256], s_sc[256], s_sh[256];
    int tid = threadIdx.x;
    for (int i = tid; i < 3*CIN; i += 256) s_w[i] = wgt[i];
    for (int i = tid; i < CIN; i += 256) { s_sc[i] = bnS[i]; s_sh[i] = bnH[i]; }
    __syncthreads();
    int idx = blockIdx.x*256 + tid;
    int p = idx % HW, b = idx / HW;
    float a0 = bias[0], a1 = bias[1], a2 = bias[2];
    const float* ip = inbuf + (size_t)b*CIN*HW + p;
#pragma unroll 4
    for (int ic = 0; ic < CIN; ++ic) {
        float v = ip[(size_t)ic*HW];
        v = fmaxf(fmaf(v, s_sc[ic], s_sh[ic]), 0.0f);
        a0 = fmaf(v, s_w[ic],        a0);
        a1 = fmaf(v, s_w[CIN+ic],    a1);
        a2 = fmaf(v, s_w[2*CIN+ic],  a2);
    }
    float r0 = base[(b*3+0)*HW + p] + a0;
    float r1 = base[(b*3+1)*HW + p] + a1;
    float r2 = base[(b*3+2)*HW + p] + a2;
    dout[(b*3+0)*HW + p] = r0;
    dout[(b*3+1)*HW + p] = r1;
    dout[(b*3+2)*HW + p] = r2;
    if (dup) {
        dup[(b*3+0)*HW + p] = r0;
        dup[(b*3+1)*HW + p] = r1;
        dup[(b*3+2)*HW + p] = r2;
    }
}

// ---------------- 2x bilinear upsample ----------------
__global__ void upsample_kernel(const float* __restrict__ src3, float* __restrict__ dst3) {
    int idx = blockIdx.x*256 + threadIdx.x;
    if (idx >= B_*3*HWF) return;
    int p = idx % HWF; int c = (idx / HWF) % 3; int b = idx / (HWF*3);
    int wo = p & 127, ho = p >> 7;
    float sx = wo*0.5f - 0.25f, sy = ho*0.5f - 0.25f;
    float x0f = floorf(sx), y0f = floorf(sy);
    float wx = sx - x0f, wy = sy - y0f;
    int x0 = (int)x0f, y0 = (int)y0f;
    int x0c = min(max(x0, 0), 63),   x1c = min(max(x0+1, 0), 63);
    int y0c = min(max(y0, 0), 63),   y1c = min(max(y0+1, 0), 63);
    const float* s = src3 + (size_t)(b*3 + c)*HWC;
    float v = s[y0c*64+x0c]*(1-wx)*(1-wy) + s[y0c*64+x1c]*wx*(1-wy)
            + s[y1c*64+x0c]*(1-wx)*wy     + s[y1c*64+x1c]*wx*wy;
    dst3[idx] = v;
}

// ---------------- host driver ----------------
extern "C" void kernel_launch(void* const* d_in, const int* in_sizes, int n_in,
                              void* d_out, int out_size) {
    const float* f0c = (const float*)d_in[0];
    const float* f1c = (const float*)d_in[1];
    const float* f0f = (const float*)d_in[2];
    const float* f1f = (const float*)d_in[3];
    const float* cw1 = (const float*)d_in[4];
    const float* cw2 = (const float*)d_in[5];
    const float* cw3 = (const float*)d_in[6];
    const float* cw4 = (const float*)d_in[7];
    const float* cw5 = (const float*)d_in[8];
    const float* cb5 = (const float*)d_in[9];
    const float* fw1 = (const float*)d_in[10];
    const float* fw2 = (const float*)d_in[11];
    const float* fw3 = (const float*)d_in[12];
    const float* fw4 = (const float*)d_in[13];
    const float* fw5 = (const float*)d_in[14];
    const float* fb5 = (const float*)d_in[15];

    float *p_cm0, *p_w1c, *p_c0, *p_c1, *p_cm, *p_up, *p_w1f, *p_f0, *p_f1;
    float *p_pv, *p_pv2, *p_bnS, *p_bnH;
    cudaGetSymbolAddress((void**)&p_cm0, g_cm0);
    cudaGetSymbolAddress((void**)&p_w1c, g_warped1c);
    cudaGetSymbolAddress((void**)&p_c0,  g_cbuf0);
    cudaGetSymbolAddress((void**)&p_c1,  g_cbuf1);
    cudaGetSymbolAddress((void**)&p_cm,  g_cm);
    cudaGetSymbolAddress((void**)&p_up,  g_up);
    cudaGetSymbolAddress((void**)&p_w1f, g_warped1f);
    cudaGetSymbolAddress((void**)&p_f0,  g_fbuf0);
    cudaGetSymbolAddress((void**)&p_f1,  g_fbuf1);
    cudaGetSymbolAddress((void**)&p_pv,  g_pv);
    cudaGetSymbolAddress((void**)&p_pv2, g_pv2);
    cudaGetSymbolAddress((void**)&p_bnS, g_bnS);
    cudaGetSymbolAddress((void**)&p_bnH, g_bnH);

    const float nC = (float)(B_*HWC), nF = (float)(B_*HWF);

    // coarse path
    attention_kernel<<<dim3(64, B_), 256>>>(f0c, f1c);
    gridsample_kernel<<<(B_*64*HWC)/256, 256>>>(f1c, p_cm0, p_w1c, 64, 64, 64);
    conv3x3_kernel<<<dim3(16, 4, B_), 256>>>(f0c, 64, 64, p_w1c, 64, 64, p_cm0, 3,
                                             cw1, p_c0, 130, 256, 64, 64,
                                             (float*)0, (float*)0, p_pv, p_pv2);
    bnreduce_kernel<<<256, 256>>>(p_pv, p_pv2, 64, nC, p_bnS+0*256, p_bnH+0*256);
    conv3x3_kernel<<<dim3(16, 4, B_), 256>>>(p_c0, 256, 256, p_c0, 256, 0, p_c0, 256,
                                             cw2, p_c1, 256, 256, 64, 64,
                                             p_bnS+0*256, p_bnH+0*256, p_pv, p_pv2);
    bnreduce_kernel<<<256, 256>>>(p_pv, p_pv2, 64, nC, p_bnS+1*256, p_bnH+1*256);
    conv3x3_kernel<<<dim3(16, 4, B_), 256>>>(p_c1, 256, 256, p_c1, 256, 0, p_c1, 256,
                                             cw3, p_c0, 256, 256, 64, 64,
                                             p_bnS+1*256, p_bnH+1*256, p_pv, p_pv2);
    bnreduce_kernel<<<256, 256>>>(p_pv, p_pv2, 64, nC, p_bnS+2*256, p_bnH+2*256);
    conv3x3_kernel<<<dim3(16, 4, B_), 256>>>(p_c0, 256, 256, p_c0, 256, 0, p_c0, 256,
                                             cw4, p_c1, 256, 256, 64, 64,
                                             p_bnS+2*256, p_bnH+2*256, p_pv, p_pv2);
    bnreduce_kernel<<<256, 256>>>(p_pv, p_pv2, 64, nC, p_bnS+3*256, p_bnH+3*256);
    conv1x1_kernel<<<(B_*HWC)/256, 256>>>(p_c1, cw5, cb5, p_cm0, (float*)d_out, p_cm,
                                          p_bnS+3*256, p_bnH+3*256, 256, HWC);

    // fine path
    upsample_kernel<<<(B_*3*HWF)/256, 256>>>(p_cm, p_up);
    gridsample_kernel<<<(B_*24*HWF)/256, 256>>>(f1f, p_up, p_w1f, 24, 128, 128);
    conv3x3_kernel<<<dim3(64, 1, B_), 256>>>(f0f, 24, 24, p_w1f, 24, 24, p_up, 3,
                                             fw1, p_f0, 50, 64, 128, 128,
                                             (float*)0, (float*)0, p_pv, p_pv2);
    bnreduce_kernel<<<64, 256>>>(p_pv, p_pv2, 256, nF, p_bnS+4*256, p_bnH+4*256);
    conv3x3_kernel<<<dim3(64, 1, B_), 256>>>(p_f0, 64, 64, p_f0, 64, 0, p_f0, 64,
                                             fw2, p_f1, 64, 64, 128, 128,
                                             p_bnS+4*256, p_bnH+4*256, p_pv, p_pv2);
    bnreduce_kernel<<<64, 256>>>(p_pv, p_pv2, 256, nF, p_bnS+5*256, p_bnH+5*256);
    conv3x3_kernel<<<dim3(64, 1, B_), 256>>>(p_f1, 64, 64, p_f1, 64, 0, p_f1, 64,
                                             fw3, p_f0, 64, 64, 128, 128,
                                             p_bnS+5*256, p_bnH+5*256, p_pv, p_pv2);
    bnreduce_kernel<<<64, 256>>>(p_pv, p_pv2, 256, nF, p_bnS+6*256, p_bnH+6*256);
    conv3x3_kernel<<<dim3(64, 1, B_), 256>>>(p_f0, 64, 64, p_f0, 64, 0, p_f0, 64,
                                             fw4, p_f1, 64, 64, 128, 128,
                                             p_bnS+6*256, p_bnH+6*256, p_pv, p_pv2);
    bnreduce_kernel<<<64, 256>>>(p_pv, p_pv2, 256, nF, p_bnS+7*256, p_bnH+7*256);
    conv1x1_kernel<<<(B_*HWF)/256, 256>>>(p_f1, fw5, fb5, p_up,
                                          (float*)d_out + B_*3*HWC, (float*)0,
                                          p_bnS+7*256, p_bnH+7*256, 64, HWF);
}